// round 15
// baseline (speedup 1.0000x reference)
#include <cuda_runtime.h>
#include <cuda_fp16.h>
#include <math.h>
#include <stdint.h>

#define BATCH 4
#define HWP 16384
#define CHW 4194304
#define TOKB 4194304
#define KC 64
#define RPH 72
#define ST 3

// ---------------- scratch ----------------
__device__ __half g_qt[BATCH * TOKB];
__device__ __half g_kt[BATCH * TOKB];
__device__ __half g_vt[BATCH * TOKB];
__device__ float  g_S3[1048576];
__device__ __half g_P[71581696];
__device__ float  g_invZ[4 * 5440];
__device__ float  g_rps[4 * 139776];
__device__ float  g_cs[131072];
__device__ float  g_cs2[131072];
__device__ __half g_attnT[BATCH * CHW];
__device__ __half g_xT[BATCH * CHW];
__device__ __half g_yT[BATCH * CHW];
__device__ __half g_WqH[65536];
__device__ __half g_WkH[65536];
__device__ __half g_WvH[65536];
__device__ __half g_WoH[589824];
__device__ float  g_mean[256];
__device__ float  g_rstd[256];

#define SOFF1 67108864ull
#define SOFF2 71303168ull
#define SOFF3 71565312ull
#define RPSB  139776

__device__ __forceinline__ int nssF(int s) { return 16384 >> (2 * (s + 1)); }
__device__ __forceinline__ int dssF(int s) { return 64 << (2 * (s + 1)); }
__device__ __forceinline__ size_t soffF(int s) { return s == 0 ? 0ull : (s == 1 ? SOFF1 : (s == 2 ? SOFF2 : SOFF3)); }

// ---------------- helpers ----------------
__device__ __forceinline__ void cpasync16(uint32_t dst, const void* src) {
    asm volatile("cp.async.cg.shared.global [%0], [%1], 16;" :: "r"(dst), "l"(src));
}
__device__ __forceinline__ void cpasync16z(uint32_t dst, const void* src, int srcsz) {
    asm volatile("cp.async.cg.shared.global [%0], [%1], 16, %2;" :: "r"(dst), "l"(src), "r"(srcsz));
}
__device__ __forceinline__ void ldsm4(uint32_t a, uint32_t& r0, uint32_t& r1, uint32_t& r2, uint32_t& r3) {
    asm volatile("ldmatrix.sync.aligned.m8n8.x4.shared.b16 {%0,%1,%2,%3}, [%4];"
                 : "=r"(r0), "=r"(r1), "=r"(r2), "=r"(r3) : "r"(a));
}
__device__ __forceinline__ void mma_f16(float* c, const uint32_t* a, const uint32_t* b) {
    asm volatile("mma.sync.aligned.m16n8k16.row.col.f32.f16.f16.f32 "
                 "{%0,%1,%2,%3}, {%4,%5,%6,%7}, {%8,%9}, {%0,%1,%2,%3};"
                 : "+f"(c[0]), "+f"(c[1]), "+f"(c[2]), "+f"(c[3])
                 : "r"(a[0]), "r"(a[1]), "r"(a[2]), "r"(a[3]), "r"(b[0]), "r"(b[1]));
}

// ---------------- shared 128x128 fp16 mainloop (issue-before-compute) ----------------
__device__ __forceinline__ void mainloop128(
    const __half* __restrict__ Ab, const __half* __restrict__ Bb,
    int lda, int ldb, int nc, int rmaxA, int rmaxB, int m0, int n0,
    __half* Asm, __half* Bsm, float (&acc)[4][4][4])
{
    int tid = threadIdx.x;
    int lane = tid & 31, wid = tid >> 5;
    int wm = wid >> 2, wn = wid & 3;
    uint32_t sA = (uint32_t)__cvta_generic_to_shared(Asm);
    uint32_t sB = (uint32_t)__cvta_generic_to_shared(Bsm);
    const uint32_t ASTR = 128 * RPH * 2, BSTR = 128 * RPH * 2;

    auto issue = [&](int c) {
        int st = c % ST;
        int k0 = c * KC;
#pragma unroll
        for (int j = 0; j < 4; j++) {
            int i = tid + j * 256;
            int row = i >> 3, seg = (i & 7) << 3;
            int ar = min(m0 + row, rmaxA);
            cpasync16(sA + st * ASTR + (uint32_t)(row * RPH + seg) * 2,
                      Ab + (size_t)ar * lda + k0 + seg);
        }
#pragma unroll
        for (int j = 0; j < 4; j++) {
            int i = tid + j * 256;
            int row = i >> 3, seg = (i & 7) << 3;
            int br = min(n0 + row, rmaxB);
            cpasync16(sB + st * BSTR + (uint32_t)(row * RPH + seg) * 2,
                      Bb + (size_t)br * ldb + k0 + seg);
        }
    };

#pragma unroll
    for (int i = 0; i < 4; i++)
#pragma unroll
        for (int j = 0; j < 4; j++)
#pragma unroll
            for (int e = 0; e < 4; e++) acc[i][j][e] = 0.f;

    int r8 = lane & 7, hi8 = (lane >> 3) & 1, hi16 = (lane >> 4) & 1;
    uint32_t aOff = (uint32_t)((wm * 64 + r8 + hi8 * 8) * RPH * 2 + hi16 * 16);
    uint32_t bOff = (uint32_t)((wn * 32 + r8 + hi8 * 8) * RPH * 2 + hi16 * 16);

    if (0 < nc) issue(0);
    asm volatile("cp.async.commit_group;");
    if (1 < nc) issue(1);
    asm volatile("cp.async.commit_group;");

    for (int c = 0; c < nc; c++) {
        asm volatile("cp.async.wait_group 1;");
        __syncthreads();
        // stage (c+2)%ST is free here (consumed at iter c-1, drained by the sync):
        // issue BEFORE compute so loads get a full compute-span of latency cover.
        if (c + 2 < nc) issue(c + 2);
        asm volatile("cp.async.commit_group;");
        {
            int st = c % ST;
            uint32_t sa = sA + st * ASTR, sb = sB + st * BSTR;
#pragma unroll
            for (int ks = 0; ks < 4; ks++) {
                uint32_t af[4][4], bf[2][4];
#pragma unroll
                for (int mt = 0; mt < 4; mt++)
                    ldsm4(sa + aOff + mt * 16 * RPH * 2 + ks * 32, af[mt][0], af[mt][1], af[mt][2], af[mt][3]);
#pragma unroll
                for (int np = 0; np < 2; np++)
                    ldsm4(sb + bOff + np * 16 * RPH * 2 + ks * 32, bf[np][0], bf[np][1], bf[np][2], bf[np][3]);
#pragma unroll
                for (int mt = 0; mt < 4; mt++)
#pragma unroll
                    for (int np = 0; np < 2; np++) {
                        uint32_t b0[2] = { bf[np][0], bf[np][2] };
                        uint32_t b1[2] = { bf[np][1], bf[np][3] };
                        mma_f16(acc[mt][np * 2 + 0], af[mt], b0);
                        mma_f16(acc[mt][np * 2 + 1], af[mt], b1);
                    }
            }
        }
    }
}

// ---------------- merged projections ----------------
#define TRP 132
__global__ __launch_bounds__(256) void k_proj(
    const __half* __restrict__ Wq, const __half* __restrict__ Wk, const __half* __restrict__ Wv,
    const __half* __restrict__ xT, const __half* __restrict__ yT,
    const float* __restrict__ bq, const float* __restrict__ bk, const float* __restrict__ bv,
    __half* __restrict__ qt, __half* __restrict__ kt, __half* __restrict__ vt)
{
    extern __shared__ __half dynsmem[];
    int which = blockIdx.z >> 2, b = blockIdx.z & 3;
    const __half* A = (which == 0 ? xT : yT) + (size_t)b * CHW;
    const __half* Bw = which == 0 ? Wq : (which == 1 ? Wk : Wv);
    const float* bias = which == 0 ? bq : (which == 1 ? bk : bv);
    __half* outp = (which == 0 ? qt : (which == 1 ? kt : vt)) + (size_t)b * TOKB;

    int m0 = blockIdx.y * 128, n0 = blockIdx.x * 128;
    float acc[4][4][4];
    mainloop128(A, Bw, 256, 256, 4, 16383, 255, m0, n0, dynsmem, dynsmem + ST * 128 * RPH, acc);

    int tid = threadIdx.x, lane = tid & 31, wid = tid >> 5;
    int wm = wid >> 2, wn = wid & 3;
    int g = lane >> 2, q2 = (lane & 3) << 1;
    int colb = n0 + wn * 32;

    float bia0[4], bia1[4];
#pragma unroll
    for (int nt = 0; nt < 4; nt++) {
        bia0[nt] = __ldg(&bias[colb + nt * 8 + q2]);
        bia1[nt] = __ldg(&bias[colb + nt * 8 + q2 + 1]);
    }

    if (which < 2) {
        int scl = colb >> 6;
        int l = scl + 1, msk = (1 << l) - 1, owlog = 7 - l;
        int dsz = 64 << (2 * l);
        size_t sbase = (size_t)scl << 20;
#pragma unroll
        for (int mt = 0; mt < 4; mt++) {
#pragma unroll
            for (int e2 = 0; e2 < 2; e2++) {
                int p = m0 + wm * 64 + mt * 16 + g + e2 * 8;
                int yy = p >> 7, xx = p & 127;
                int wy = yy >> l, py = yy & msk, wx = xx >> l, px = xx & msk;
                int n = (wy << owlog) | wx;
                int pix = (py << l) | px;
#pragma unroll
                for (int nt = 0; nt < 4; nt++) {
                    int cl = (colb + nt * 8 + q2) & 63;
                    __half v0 = __float2half_rn(acc[mt][nt][e2 * 2 + 0] + bia0[nt]);
                    __half v1 = __float2half_rn(acc[mt][nt][e2 * 2 + 1] + bia1[nt]);
                    *(__half2*)&outp[sbase + (size_t)n * dsz + pix * 64 + cl] = __halves2half2(v0, v1);
                }
            }
        }
    } else {
        __syncthreads();
        __half* T = dynsmem;
#pragma unroll
        for (int mt = 0; mt < 4; mt++) {
#pragma unroll
            for (int e2 = 0; e2 < 2; e2++) {
                int row = wm * 64 + mt * 16 + g + e2 * 8;
#pragma unroll
                for (int nt = 0; nt < 4; nt++) {
                    int col = wn * 32 + nt * 8 + q2;
                    __half v0 = __float2half_rn(acc[mt][nt][e2 * 2 + 0] + bia0[nt]);
                    __half v1 = __float2half_rn(acc[mt][nt][e2 * 2 + 1] + bia1[nt]);
                    *(__half2*)&T[row * TRP + col] = __halves2half2(v0, v1);
                }
            }
        }
        __syncthreads();
        int yrow = blockIdx.y;
#pragma unroll
        for (int i = 0; i < 8; i++) {
            int t = tid * 8 + i;
            int h = t >> 10, ht = t & 1023;
            int cl = ht >> 4, sub = ht & 15;
            int scl = (n0 >> 6) + h;
            int l = scl + 1;
            int px = sub >> (4 - l);
            int chunk = sub & ((16 >> l) - 1);
            int nTokS = 16384 >> (2 * l);
            int py = yrow & ((1 << l) - 1);
            int wy = yrow >> l;
            int d = ((py << l) | px) * 64 + cl;
            int nst = (wy << (7 - l)) + chunk * 8;
            uint4 u;
            __half* tp = (__half*)&u;
#pragma unroll
            for (int r = 0; r < 8; r++) {
                int xx = ((chunk * 8 + r) << l) | px;
                tp[r] = T[xx * TRP + h * 64 + cl];
            }
            *(uint4*)&outp[((size_t)scl << 20) + (size_t)d * nTokS + nst] = u;
        }
    }
}

// ---------------- merged scores: fused exp -> P fp16; partial row sums ----------------
__global__ __launch_bounds__(256) void k_scores(
    const __half* __restrict__ qt, const __half* __restrict__ kt,
    __half* __restrict__ P, float* __restrict__ S3, float* __restrict__ rps)
{
    extern __shared__ __half dynsmem[];
    int f = blockIdx.x;
    int s, b, zS, sp = 0, bx, by;
    if (f < 4096)      { s = 0; zS = f >> 10; b = zS; int t = f & 1023; by = t >> 5; bx = t & 31; }
    else if (f < 4352) { s = 1; int r = f - 4096; zS = r >> 6; b = zS; int t = r & 63; by = t >> 3; bx = t & 7; }
    else if (f < 4368) { s = 2; int r = f - 4352; zS = r >> 2; b = zS; int t = r & 3; by = t >> 1; bx = t & 1; }
    else               { s = 3; int zz = f - 4368; zS = zz; b = zz >> 6; sp = zz & 63; bx = 0; by = 0; }

    int nTok = nssF(s), d = dssF(s);
    int Kl = (s == 3) ? 256 : d;
    const __half* Ab = qt + (size_t)b * TOKB + ((size_t)s << 20) + (size_t)sp * 256;
    const __half* Bb = kt + (size_t)b * TOKB + ((size_t)s << 20) + (size_t)sp * 256;
    int m0 = by * 128, n0 = bx * 128;

    float acc[4][4][4];
    mainloop128(Ab, Bb, d, d, Kl / KC, nTok - 1, nTok - 1, m0, n0,
                dynsmem, dynsmem + ST * 128 * RPH, acc);

    int tid = threadIdx.x, lane = tid & 31, wid = tid >> 5;
    int wm = wid >> 2, wn = wid & 3;
    int g = lane >> 2, q2 = (lane & 3) << 1;

    if (s < 3) {
        __syncthreads();
        float* sred = (float*)dynsmem;
        float alpha = rsqrtf((float)d);
        __half* Pb = P + soffF(s) + (size_t)zS * nTok * nTok;
#pragma unroll
        for (int mt = 0; mt < 4; mt++) {
            int row0 = m0 + wm * 64 + mt * 16 + g;
#pragma unroll
            for (int e2 = 0; e2 < 2; e2++) {
                int row = row0 + e2 * 8;
                float rs = 0.f;
#pragma unroll
                for (int nt = 0; nt < 4; nt++) {
                    int col = n0 + wn * 32 + nt * 8 + q2;
                    float e0 = __expf(acc[mt][nt][e2 * 2 + 0] * alpha);
                    float e1 = __expf(acc[mt][nt][e2 * 2 + 1] * alpha);
                    rs += e0 + e1;
                    *(__half2*)&Pb[(size_t)row * nTok + col] = __floats2half2_rn(e0, e1);
                }
                rs += __shfl_xor_sync(0xffffffff, rs, 1);
                rs += __shfl_xor_sync(0xffffffff, rs, 2);
                if ((lane & 3) == 0)
                    sred[(wm * 64 + mt * 16 + g + e2 * 8) * 4 + wn] = rs;
            }
        }
        __syncthreads();
        if (tid < 128) {
            float tot = sred[tid * 4] + sred[tid * 4 + 1] + sred[tid * 4 + 2] + sred[tid * 4 + 3];
            int nb = nTok >> 7;
            int base = (s == 0) ? 0 : (s == 1 ? 131072 : 139264);
            rps[b * RPSB + base + (m0 + tid) * nb + bx] = tot;
        }
    } else {
        float* Sb = S3 + (size_t)zS * 4096;
#pragma unroll
        for (int mt = 0; mt < 4; mt++) {
            int row0 = m0 + wm * 64 + mt * 16 + g;
#pragma unroll
            for (int e2 = 0; e2 < 2; e2++) {
                int row = row0 + e2 * 8;
                if (row >= 64) continue;
#pragma unroll
                for (int nt = 0; nt < 4; nt++) {
                    int col = n0 + wn * 32 + nt * 8 + q2;
                    if (col >= 64) continue;
                    *(float2*)&Sb[(size_t)row * 64 + col] =
                        make_float2(acc[mt][nt][e2 * 2 + 0], acc[mt][nt][e2 * 2 + 1]);
                }
            }
        }
    }
}

// ---------------- norm ----------------
__global__ void k_norm(const float* __restrict__ rps, const float* __restrict__ S3,
                       __half* __restrict__ P3out, float* __restrict__ invZ)
{
    __shared__ float red[128];
    int f = blockIdx.x;
    int b = blockIdx.y;
    int tid = threadIdx.x;

    if (f < 5376) {
        int s, row;
        if (f < 4096)      { s = 0; row = f; }
        else if (f < 5120) { s = 1; row = f - 4096; }
        else               { s = 2; row = f - 5120; }
        int nb = nssF(s) >> 7;
        int base = (s == 0) ? 0 : (s == 1 ? 131072 : 139264);
        if (tid < 32) {
            float v = (tid < nb) ? rps[b * RPSB + base + row * nb + tid] : 0.f;
            v += __shfl_xor_sync(0xffffffff, v, 16);
            v += __shfl_xor_sync(0xffffffff, v, 8);
            v += __shfl_xor_sync(0xffffffff, v, 4);
            v += __shfl_xor_sync(0xffffffff, v, 2);
            v += __shfl_xor_sync(0xffffffff, v, 1);
            if (tid == 0) invZ[b * 5440 + f] = 1.0f / v;
        }
    } else {
        int row = f - 5376;
        float e = 0.f;
        if (tid < 64) {
            float sv = 0.f;
            for (int sp = 0; sp < 64; sp++)
                sv += S3[(size_t)((b << 6) + sp) * 4096 + row * 64 + tid];
            e = __expf(sv * 0.0078125f);
            P3out[SOFF3 + (size_t)b * 4096 + row * 64 + tid] = __float2half_rn(e);
        }
        red[tid] = e; __syncthreads();
        for (int st = 64; st; st >>= 1) { if (tid < st) red[tid] += red[tid + st]; __syncthreads(); }
        if (tid == 0) invZ[b * 5440 + f] = 1.0f / red[0];
    }
}

// ---------------- merged P@V ----------------
__global__ __launch_bounds__(256) void k_pv(
    const __half* __restrict__ P, const __half* __restrict__ vt,
    const float* __restrict__ invZ, __half* __restrict__ attnT)
{
    extern __shared__ __half dynsmem[];
    int f = blockIdx.x;
    int s, b, bx, by;
    if (f < 256)      { s = 0; b = f >> 6; int t = f & 63; by = t >> 1; bx = t & 1; }
    else if (f < 512) { s = 1; int r = f - 256; b = r >> 6; int t = r & 63; by = t >> 3; bx = t & 7; }
    else if (f < 768) { s = 2; int r = f - 512; b = r >> 6; int t = r & 63; bx = t >> 1; by = t & 1; }
    else              { s = 3; int r = f - 768; b = r >> 7; bx = r & 127; by = 0; }

    int nTok = nssF(s), d = dssF(s);
    const __half* Ab = P + soffF(s) + (size_t)b * nTok * nTok;
    const __half* Bb = vt + (size_t)b * TOKB + ((size_t)s << 20);
    int m0 = by * 128, n0 = bx * 128;

    float acc[4][4][4];
    mainloop128(Ab, Bb, nTok, nTok, nTok / KC, nTok - 1, d - 1, m0, n0,
                dynsmem, dynsmem + ST * 128 * RPH, acc);

    int tid = threadIdx.x, lane = tid & 31, wid = tid >> 5;
    int wm = wid >> 2, wn = wid & 3;
    int g = lane >> 2, q2 = (lane & 3) << 1;

    int l = s + 1, msk = (1 << l) - 1, owlog = 7 - l;
    int colb = n0 + wn * 32;
    int pix = colb >> 6;
    int py = pix >> l, px = pix & msk;
    int rowbase = (s == 0) ? 0 : (s == 1 ? 4096 : (s == 2 ? 5120 : 5376));

#pragma unroll
    for (int mt = 0; mt < 4; mt++) {
        int row0 = m0 + wm * 64 + mt * 16 + g;
#pragma unroll
        for (int e2 = 0; e2 < 2; e2++) {
            int row = row0 + e2 * 8;
            if (row >= nTok) continue;
            float iz = __ldg(&invZ[b * 5440 + rowbase + row]);
            int wy = row >> owlog, wx = row & ((1 << owlog) - 1);
            int y = (wy << l) | py, x = (wx << l) | px;
            size_t pbase = ((((size_t)b << 14) + (y << 7) + x) << 8) + (s << 6);
#pragma unroll
            for (int nt = 0; nt < 4; nt++) {
                int cl = (colb + nt * 8 + q2) & 63;
                __half v0 = __float2half_rn(acc[mt][nt][e2 * 2 + 0] * iz);
                __half v1 = __float2half_rn(acc[mt][nt][e2 * 2 + 1] * iz);
                *(__half2*)&attnT[pbase + cl] = __halves2half2(v0, v1);
            }
        }
    }
}

// ---------------- conv3x3 tap-GEMM + channel stats partials ----------------
__global__ __launch_bounds__(256) void k_conv(
    const __half* __restrict__ Wo, const __half* __restrict__ attnT,
    const float* __restrict__ bo, float* __restrict__ out,
    float* __restrict__ cs, float* __restrict__ cs2)
{
    extern __shared__ __half dynsmem[];
    __half* Asm = dynsmem;
    __half* Bsm = dynsmem + ST * 128 * RPH;
    int tid = threadIdx.x;
    int lane = tid & 31, wid = tid >> 5;
    int wm = wid >> 2, wn = wid & 3;
    int m0 = blockIdx.y * 128, n0 = blockIdx.x * 128;
    int bidx = blockIdx.z;
    const __half* Ab = Wo;
    const __half* Bb = attnT + (size_t)bidx * CHW;

    uint32_t sA = (uint32_t)__cvta_generic_to_shared(Asm);
    uint32_t sB = (uint32_t)__cvta_generic_to_shared(Bsm);
    const uint32_t ASTR = 128 * RPH * 2, BSTR = 128 * RPH * 2;
    const int nc = 36;

    auto issue = [&](int c) {
        int st = c % ST;
        int k0 = c * KC;
#pragma unroll
        for (int j = 0; j < 4; j++) {
            int i = tid + j * 256;
            int row = i >> 3, seg = (i & 7) << 3;
            cpasync16(sA + st * ASTR + (uint32_t)(row * RPH + seg) * 2,
                      Ab + (size_t)(m0 + row) * 2304 + k0 + seg);
        }
        int tap = k0 >> 8;
        int dy = tap / 3, dx = tap - dy * 3;
        int gy = (int)blockIdx.x + dy - 1;
        bool okY = (unsigned)gy < 128u;
#pragma unroll
        for (int j = 0; j < 4; j++) {
            int i = tid + j * 256;
            int xrow = i >> 3, seg = (i & 7) << 3;
            int ch = (k0 & 255) + seg;
            int gx = xrow + dx - 1;
            int sz = (okY && (unsigned)gx < 128u) ? 16 : 0;
            const __half* src = Bb + ((size_t)(gy << 7) + gx) * 256 + ch;
            cpasync16z(sB + st * BSTR + (uint32_t)(xrow * RPH + seg) * 2, src, sz);
        }
    };

    float acc[4][4][4];
#pragma unroll
    for (int i = 0; i < 4; i++)
#pragma unroll
        for (int j = 0; j < 4; j++)
#pragma unroll
            for (int e = 0; e < 4; e++) acc[i][j][e] = 0.f;

    int r8 = lane & 7, hi8 = (lane >> 3) & 1, hi16 = (lane >> 4) & 1;
    uint32_t aOff = (uint32_t)((wm * 64 + r8 + hi8 * 8) * RPH * 2 + hi16 * 16);
    uint32_t bOff = (uint32_t)((wn * 32 + r8 + hi8 * 8) * RPH * 2 + hi16 * 16);

    issue(0);
    asm volatile("cp.async.commit_group;");
    issue(1);
    asm volatile("cp.async.commit_group;");

    for (int c = 0; c < nc; c++) {
        asm volatile("cp.async.wait_group 1;");
        __syncthreads();
        if (c + 2 < nc) issue(c + 2);
        asm volatile("cp.async.commit_group;");
        {
            int st = c % ST;
            uint32_t sa = sA + st * ASTR, sb = sB + st * BSTR;
#pragma unroll
            for (int ks = 0; ks < 4; ks++) {
                uint32_t af[4][4], bf[2][4];
#pragma unroll
                for (int mt = 0; mt < 4; mt++)
                    ldsm4(sa + aOff + mt * 16 * RPH * 2 + ks * 32, af[mt][0], af[mt][1], af[mt][2], af[mt][3]);
#pragma unroll
                for (int np = 0; np < 2; np++)
                    ldsm4(sb + bOff + np * 16 * RPH * 2 + ks * 32, bf[np][0], bf[np][1], bf[np][2], bf[np][3]);
#pragma unroll
                for (int mt = 0; mt < 4; mt++)
#pragma unroll
                    for (int np = 0; np < 2; np++) {
                        uint32_t b0[2] = { bf[np][0], bf[np][2] };
                        uint32_t b1[2] = { bf[np][1], bf[np][3] };
                        mma_f16(acc[mt][np * 2 + 0], af[mt], b0);
                        mma_f16(acc[mt][np * 2 + 1], af[mt], b1);
                    }
            }
        }
    }

    __syncthreads();
    float* sred  = (float*)dynsmem;
    float* sred2 = sred + 512;
    int g = lane >> 2, q2 = (lane & 3) << 1;
#pragma unroll
    for (int mt = 0; mt < 4; mt++) {
        int row0 = m0 + wm * 64 + mt * 16 + g;
#pragma unroll
        for (int e2 = 0; e2 < 2; e2++) {
            int row = row0 + e2 * 8;
            float bia = __ldg(&bo[row]);
            float rs = 0.f, rs2 = 0.f;
#pragma unroll
            for (int nt = 0; nt < 4; nt++) {
                int col = n0 + wn * 32 + nt * 8 + q2;
                float v0 = acc[mt][nt][e2 * 2 + 0] + bia;
                float v1 = acc[mt][nt][e2 * 2 + 1] + bia;
                rs += v0 + v1;
                rs2 += v0 * v0 + v1 * v1;
                size_t adr = (((size_t)bidx * 256 + row) << 14) + col;
                *(float2*)&out[adr] = make_float2(v0, v1);
            }
            rs  += __shfl_xor_sync(0xffffffff, rs, 1);
            rs  += __shfl_xor_sync(0xffffffff, rs, 2);
            rs2 += __shfl_xor_sync(0xffffffff, rs2, 1);
            rs2 += __shfl_xor_sync(0xffffffff, rs2, 2);
            if ((lane & 3) == 0) {
                int rl = wm * 64 + mt * 16 + g + e2 * 8;
                sred[rl * 4 + wn]  = rs;
                sred2[rl * 4 + wn] = rs2;
            }
        }
    }
    __syncthreads();
    if (tid < 128) {
        float s1 = sred[tid * 4] + sred[tid * 4 + 1] + sred[tid * 4 + 2] + sred[tid * 4 + 3];
        float s2 = sred2[tid * 4] + sred2[tid * 4 + 1] + sred2[tid * 4 + 2] + sred2[tid * 4 + 3];
        int ch = m0 + tid;
        int slot = bidx * 128 + blockIdx.x;
        cs[ch * 512 + slot]  = s1;
        cs2[ch * 512 + slot] = s2;
    }
}

// ---------------- prep ----------------
__global__ void k_prepW(const float* __restrict__ wq, const float* __restrict__ wk, const float* __restrict__ wv,
                        const float* __restrict__ wo,
                        __half* __restrict__ dq, __half* __restrict__ dk, __half* __restrict__ dv,
                        __half* __restrict__ dwo)
{
    int i = blockIdx.x * 256 + threadIdx.x;
    if (i < 65536) dq[i] = __float2half_rn(wq[i]);
    else if (i < 131072) dk[i - 65536] = __float2half_rn(wk[i - 65536]);
    else if (i < 196608) dv[i - 131072] = __float2half_rn(wv[i - 131072]);
    else {
        int j = i - 196608;
        if (j < 589824) {
            int o = j / 2304, r = j - o * 2304;
            int tap = r >> 8, c = r & 255;
            dwo[j] = __float2half_rn(wo[((size_t)o * 256 + c) * 9 + tap]);
        }
    }
}

__global__ void k_transpose2(const float* __restrict__ xs, const float* __restrict__ ys,
                             __half* __restrict__ xd, __half* __restrict__ yd)
{
    __shared__ float t[32][33];
    int zz = blockIdx.z;
    int b = zz & 3;
    const float* s = ((zz >> 2) ? ys : xs) + (size_t)b * CHW;
    __half* d = ((zz >> 2) ? yd : xd) + (size_t)b * CHW;
    int x = blockIdx.x * 32 + threadIdx.x;
    int yc = blockIdx.y * 32 + threadIdx.y;
#pragma unroll
    for (int j = 0; j < 4; j++)
        t[threadIdx.y + j * 8][threadIdx.x] = s[(size_t)(yc + j * 8) * HWP + x];
    __syncthreads();
    int x2 = blockIdx.y * 32 + threadIdx.x;
    int y2 = blockIdx.x * 32 + threadIdx.y;
#pragma unroll
    for (int j = 0; j < 4; j++)
        d[(size_t)(y2 + j * 8) * 256 + x2] = __float2half_rn(t[threadIdx.x][threadIdx.y + j * 8]);
}

// ---------------- batchnorm stats from conv partials ----------------
__global__ void k_stats(const float* __restrict__ cs, const float* __restrict__ cs2,
                        float* __restrict__ meanv, float* __restrict__ rstdv)
{
    __shared__ float rs[256], rs2[256];
    int c = blockIdx.x;
    int tid = threadIdx.x;
    float s  = cs[c * 512 + tid]  + cs[c * 512 + 256 + tid];
    float s2 = cs2[c * 512 + tid] + cs2[c * 512 + 256 + tid];
    rs[tid] = s; rs2[tid] = s2; __syncthreads();
    for (int st = 128; st; st >>= 1) {
        if (tid < st) { rs[tid] += rs[tid + st]; rs2[tid] += rs2[tid + st]; }
        __syncthreads();
    }
    if (tid == 0) {
        float m = rs[0] * (1.0f / 65536.0f);
        float var = rs2[0] * (1.0f / 65536.0f) - m * m;
        meanv[c] = m;
        rstdv[c] = rsqrtf(var + 1e-5f);
    }
}

// ---------------- normalize + affine + LeakyReLU ----------------
__global__ void k_final(float* __restrict__ z, const float* __restrict__ meanv, const float* __restrict__ rstdv,
                        const float* __restrict__ gamma, const float* __restrict__ beta)
{
    size_t idx = ((size_t)blockIdx.x * 1024 + threadIdx.x) * 4;
    int c = (int)((idx >> 14) & 255);
    float m = __ldg(&meanv[c]);
    float sc = __ldg(&rstdv[c]) * __ldg(&gamma[c]);
    float bt = __ldg(&beta[c]);
    float4 v = *(float4*)&z[idx];
    v.x = (v.x - m) * sc + bt; v.y = (v.y - m) * sc + bt;
    v.z = (v.z - m) * sc + bt; v.w = (v.w - m) * sc + bt;
    v.x = v.x >= 0.f ? v.x : 0.2f * v.x;
    v.y = v.y >= 0.f ? v.y : 0.2f * v.y;
    v.z = v.z >= 0.f ? v.z : 0.2f * v.z;
    v.w = v.w >= 0.f ? v.w : 0.2f * v.w;
    *(float4*)&z[idx] = v;
}

// ---------------- host launch ----------------
extern "C" void kernel_launch(void* const* d_in, const int* in_sizes, int n_in,
                              void* d_out, int out_size)
{
    (void)in_sizes; (void)n_in; (void)out_size;
    const float* x     = (const float*)d_in[0];
    const float* y     = (const float*)d_in[1];
    const float* Wq    = (const float*)d_in[2];
    const float* bq    = (const float*)d_in[3];
    const float* Wk    = (const float*)d_in[4];
    const float* bk    = (const float*)d_in[5];
    const float* Wv    = (const float*)d_in[6];
    const float* bv    = (const float*)d_in[7];
    const float* Wo    = (const float*)d_in[8];
    const float* bo    = (const float*)d_in[9];
    const float* gamma = (const float*)d_in[10];
    const float* beta  = (const float*)d_in[11];
    float* out = (float*)d_out;

    __half *qt, *kt, *vt, *P, *attnT, *xT, *yT, *WqH, *WkH, *WvH, *WoH;
    float *S3, *invZ, *rps, *cs, *cs2, *meanv, *rstdv;
    cudaGetSymbolAddress((void**)&qt,    g_qt);
    cudaGetSymbolAddress((void**)&kt,    g_kt);
    cudaGetSymbolAddress((void**)&vt,    g_vt);
    cudaGetSymbolAddress((void**)&S3,    g_S3);
    cudaGetSymbolAddress((void**)&P,     g_P);
    cudaGetSymbolAddress((void**)&invZ,  g_invZ);
    cudaGetSymbolAddress((void**)&rps,   g_rps);
    cudaGetSymbolAddress((void**)&cs,    g_cs);
    cudaGetSymbolAddress((void**)&cs2,   g_cs2);
    cudaGetSymbolAddress((void**)&attnT, g_attnT);
    cudaGetSymbolAddress((void**)&xT,    g_xT);
    cudaGetSymbolAddress((void**)&yT,    g_yT);
    cudaGetSymbolAddress((void**)&WqH,   g_WqH);
    cudaGetSymbolAddress((void**)&WkH,   g_WkH);
    cudaGetSymbolAddress((void**)&WvH,   g_WvH);
    cudaGetSymbolAddress((void**)&WoH,   g_WoH);
    cudaGetSymbolAddress((void**)&meanv, g_mean);
    cudaGetSymbolAddress((void**)&rstdv, g_rstd);

    const int shm = ST * (128 + 128) * RPH * 2;   // 110592
    cudaFuncSetAttribute(k_proj,   cudaFuncAttributeMaxDynamicSharedMemorySize, shm);
    cudaFuncSetAttribute(k_scores, cudaFuncAttributeMaxDynamicSharedMemorySize, shm);
    cudaFuncSetAttribute(k_pv,     cudaFuncAttributeMaxDynamicSharedMemorySize, shm);
    cudaFuncSetAttribute(k_conv,   cudaFuncAttributeMaxDynamicSharedMemorySize, shm);

    // prep
    k_prepW<<<3072, 256>>>(Wq, Wk, Wv, Wo, WqH, WkH, WvH, WoH);
    k_transpose2<<<dim3(512, 8, 8), dim3(32, 8)>>>(x, y, xT, yT);

    // merged stages
    k_proj<<<dim3(2, 128, 12), 256, shm>>>(WqH, WkH, WvH, xT, yT, bq, bk, bv, qt, kt, vt);
    k_scores<<<4624, 256, shm>>>(qt, kt, P, S3, rps);
    k_norm<<<dim3(5440, 4), 128>>>(rps, S3, P, invZ);
    k_pv<<<1280, 256, shm>>>(P, vt, invZ, attnT);
    k_conv<<<dim3(128, 2, 4), 256, shm>>>(WoH, attnT, bo, out, cs, cs2);
    k_stats<<<256, 256>>>(cs, cs2, meanv, rstdv);
    k_final<<<4096, 1024>>>(out, meanv, rstdv, gamma, beta);
}

// round 16
// speedup vs baseline: 1.0224x; 1.0224x over previous
#include <cuda_runtime.h>
#include <cuda_fp16.h>
#include <math.h>
#include <stdint.h>

#define BATCH 4
#define HWP 16384
#define CHW 4194304
#define TOKB 4194304
#define KC 64
#define RPH 72
#define ST 3

// ---------------- scratch ----------------
__device__ __half g_qt[BATCH * TOKB];
__device__ __half g_kt[BATCH * TOKB];
__device__ __half g_vt[BATCH * TOKB];
__device__ float  g_S3[1048576];
__device__ __half g_P[71581696];
__device__ float  g_invZ[4 * 5440];        // only scale-3 rows used now
__device__ float  g_rps[4 * 139776];
__device__ float  g_cs[131072];
__device__ float  g_cs2[131072];
__device__ __half g_attnT[BATCH * CHW];
__device__ __half g_xT[BATCH * CHW];
__device__ __half g_yT[BATCH * CHW];
__device__ __half g_WqH[65536];
__device__ __half g_WkH[65536];
__device__ __half g_WvH[65536];
__device__ __half g_WoH[589824];
__device__ float  g_mean[256];
__device__ float  g_rstd[256];

#define SOFF1 67108864ull
#define SOFF2 71303168ull
#define SOFF3 71565312ull
#define RPSB  139776

__device__ __forceinline__ int nssF(int s) { return 16384 >> (2 * (s + 1)); }
__device__ __forceinline__ int dssF(int s) { return 64 << (2 * (s + 1)); }
__device__ __forceinline__ size_t soffF(int s) { return s == 0 ? 0ull : (s == 1 ? SOFF1 : (s == 2 ? SOFF2 : SOFF3)); }

// ---------------- helpers ----------------
__device__ __forceinline__ void cpasync16(uint32_t dst, const void* src) {
    asm volatile("cp.async.cg.shared.global [%0], [%1], 16;" :: "r"(dst), "l"(src));
}
__device__ __forceinline__ void cpasync16z(uint32_t dst, const void* src, int srcsz) {
    asm volatile("cp.async.cg.shared.global [%0], [%1], 16, %2;" :: "r"(dst), "l"(src), "r"(srcsz));
}
__device__ __forceinline__ void ldsm4(uint32_t a, uint32_t& r0, uint32_t& r1, uint32_t& r2, uint32_t& r3) {
    asm volatile("ldmatrix.sync.aligned.m8n8.x4.shared.b16 {%0,%1,%2,%3}, [%4];"
                 : "=r"(r0), "=r"(r1), "=r"(r2), "=r"(r3) : "r"(a));
}
__device__ __forceinline__ void mma_f16(float* c, const uint32_t* a, const uint32_t* b) {
    asm volatile("mma.sync.aligned.m16n8k16.row.col.f32.f16.f16.f32 "
                 "{%0,%1,%2,%3}, {%4,%5,%6,%7}, {%8,%9}, {%0,%1,%2,%3};"
                 : "+f"(c[0]), "+f"(c[1]), "+f"(c[2]), "+f"(c[3])
                 : "r"(a[0]), "r"(a[1]), "r"(a[2]), "r"(a[3]), "r"(b[0]), "r"(b[1]));
}

// ---------------- shared 128x128 fp16 mainloop (R14 ordering) ----------------
__device__ __forceinline__ void mainloop128(
    const __half* __restrict__ Ab, const __half* __restrict__ Bb,
    int lda, int ldb, int nc, int rmaxA, int rmaxB, int m0, int n0,
    __half* Asm, __half* Bsm, float (&acc)[4][4][4])
{
    int tid = threadIdx.x;
    int lane = tid & 31, wid = tid >> 5;
    int wm = wid >> 2, wn = wid & 3;
    uint32_t sA = (uint32_t)__cvta_generic_to_shared(Asm);
    uint32_t sB = (uint32_t)__cvta_generic_to_shared(Bsm);
    const uint32_t ASTR = 128 * RPH * 2, BSTR = 128 * RPH * 2;

    auto issue = [&](int c) {
        int st = c % ST;
        int k0 = c * KC;
#pragma unroll
        for (int j = 0; j < 4; j++) {
            int i = tid + j * 256;
            int row = i >> 3, seg = (i & 7) << 3;
            int ar = min(m0 + row, rmaxA);
            cpasync16(sA + st * ASTR + (uint32_t)(row * RPH + seg) * 2,
                      Ab + (size_t)ar * lda + k0 + seg);
        }
#pragma unroll
        for (int j = 0; j < 4; j++) {
            int i = tid + j * 256;
            int row = i >> 3, seg = (i & 7) << 3;
            int br = min(n0 + row, rmaxB);
            cpasync16(sB + st * BSTR + (uint32_t)(row * RPH + seg) * 2,
                      Bb + (size_t)br * ldb + k0 + seg);
        }
    };

#pragma unroll
    for (int i = 0; i < 4; i++)
#pragma unroll
        for (int j = 0; j < 4; j++)
#pragma unroll
            for (int e = 0; e < 4; e++) acc[i][j][e] = 0.f;

    int r8 = lane & 7, hi8 = (lane >> 3) & 1, hi16 = (lane >> 4) & 1;
    uint32_t aOff = (uint32_t)((wm * 64 + r8 + hi8 * 8) * RPH * 2 + hi16 * 16);
    uint32_t bOff = (uint32_t)((wn * 32 + r8 + hi8 * 8) * RPH * 2 + hi16 * 16);

    if (0 < nc) issue(0);
    asm volatile("cp.async.commit_group;");
    if (1 < nc) issue(1);
    asm volatile("cp.async.commit_group;");

    for (int c = 0; c < nc; c++) {
        asm volatile("cp.async.wait_group 1;");
        __syncthreads();
        {
            int st = c % ST;
            uint32_t sa = sA + st * ASTR, sb = sB + st * BSTR;
#pragma unroll
            for (int ks = 0; ks < 4; ks++) {
                uint32_t af[4][4], bf[2][4];
#pragma unroll
                for (int mt = 0; mt < 4; mt++)
                    ldsm4(sa + aOff + mt * 16 * RPH * 2 + ks * 32, af[mt][0], af[mt][1], af[mt][2], af[mt][3]);
#pragma unroll
                for (int np = 0; np < 2; np++)
                    ldsm4(sb + bOff + np * 16 * RPH * 2 + ks * 32, bf[np][0], bf[np][1], bf[np][2], bf[np][3]);
#pragma unroll
                for (int mt = 0; mt < 4; mt++)
#pragma unroll
                    for (int np = 0; np < 2; np++) {
                        uint32_t b0[2] = { bf[np][0], bf[np][2] };
                        uint32_t b1[2] = { bf[np][1], bf[np][3] };
                        mma_f16(acc[mt][np * 2 + 0], af[mt], b0);
                        mma_f16(acc[mt][np * 2 + 1], af[mt], b1);
                    }
            }
        }
        if (c + 2 < nc) issue(c + 2);
        asm volatile("cp.async.commit_group;");
    }
}

// ---------------- merged projections ----------------
#define TRP 132
__global__ __launch_bounds__(256) void k_proj(
    const __half* __restrict__ Wq, const __half* __restrict__ Wk, const __half* __restrict__ Wv,
    const __half* __restrict__ xT, const __half* __restrict__ yT,
    const float* __restrict__ bq, const float* __restrict__ bk, const float* __restrict__ bv,
    __half* __restrict__ qt, __half* __restrict__ kt, __half* __restrict__ vt)
{
    extern __shared__ __half dynsmem[];
    int which = blockIdx.z >> 2, b = blockIdx.z & 3;
    const __half* A = (which == 0 ? xT : yT) + (size_t)b * CHW;
    const __half* Bw = which == 0 ? Wq : (which == 1 ? Wk : Wv);
    const float* bias = which == 0 ? bq : (which == 1 ? bk : bv);
    __half* outp = (which == 0 ? qt : (which == 1 ? kt : vt)) + (size_t)b * TOKB;

    int m0 = blockIdx.y * 128, n0 = blockIdx.x * 128;
    float acc[4][4][4];
    mainloop128(A, Bw, 256, 256, 4, 16383, 255, m0, n0, dynsmem, dynsmem + ST * 128 * RPH, acc);

    int tid = threadIdx.x, lane = tid & 31, wid = tid >> 5;
    int wm = wid >> 2, wn = wid & 3;
    int g = lane >> 2, q2 = (lane & 3) << 1;
    int colb = n0 + wn * 32;

    float bia0[4], bia1[4];
#pragma unroll
    for (int nt = 0; nt < 4; nt++) {
        bia0[nt] = __ldg(&bias[colb + nt * 8 + q2]);
        bia1[nt] = __ldg(&bias[colb + nt * 8 + q2 + 1]);
    }

    if (which < 2) {
        int scl = colb >> 6;
        int l = scl + 1, msk = (1 << l) - 1, owlog = 7 - l;
        int dsz = 64 << (2 * l);
        size_t sbase = (size_t)scl << 20;
#pragma unroll
        for (int mt = 0; mt < 4; mt++) {
#pragma unroll
            for (int e2 = 0; e2 < 2; e2++) {
                int p = m0 + wm * 64 + mt * 16 + g + e2 * 8;
                int yy = p >> 7, xx = p & 127;
                int wy = yy >> l, py = yy & msk, wx = xx >> l, px = xx & msk;
                int n = (wy << owlog) | wx;
                int pix = (py << l) | px;
#pragma unroll
                for (int nt = 0; nt < 4; nt++) {
                    int cl = (colb + nt * 8 + q2) & 63;
                    __half v0 = __float2half_rn(acc[mt][nt][e2 * 2 + 0] + bia0[nt]);
                    __half v1 = __float2half_rn(acc[mt][nt][e2 * 2 + 1] + bia1[nt]);
                    *(__half2*)&outp[sbase + (size_t)n * dsz + pix * 64 + cl] = __halves2half2(v0, v1);
                }
            }
        }
    } else {
        __syncthreads();
        __half* T = dynsmem;
#pragma unroll
        for (int mt = 0; mt < 4; mt++) {
#pragma unroll
            for (int e2 = 0; e2 < 2; e2++) {
                int row = wm * 64 + mt * 16 + g + e2 * 8;
#pragma unroll
                for (int nt = 0; nt < 4; nt++) {
                    int col = wn * 32 + nt * 8 + q2;
                    __half v0 = __float2half_rn(acc[mt][nt][e2 * 2 + 0] + bia0[nt]);
                    __half v1 = __float2half_rn(acc[mt][nt][e2 * 2 + 1] + bia1[nt]);
                    *(__half2*)&T[row * TRP + col] = __halves2half2(v0, v1);
                }
            }
        }
        __syncthreads();
        int yrow = blockIdx.y;
#pragma unroll
        for (int i = 0; i < 8; i++) {
            int t = tid * 8 + i;
            int h = t >> 10, ht = t & 1023;
            int cl = ht >> 4, sub = ht & 15;
            int scl = (n0 >> 6) + h;
            int l = scl + 1;
            int px = sub >> (4 - l);
            int chunk = sub & ((16 >> l) - 1);
            int nTokS = 16384 >> (2 * l);
            int py = yrow & ((1 << l) - 1);
            int wy = yrow >> l;
            int d = ((py << l) | px) * 64 + cl;
            int nst = (wy << (7 - l)) + chunk * 8;
            uint4 u;
            __half* tp = (__half*)&u;
#pragma unroll
            for (int r = 0; r < 8; r++) {
                int xx = ((chunk * 8 + r) << l) | px;
                tp[r] = T[xx * TRP + h * 64 + cl];
            }
            *(uint4*)&outp[((size_t)scl << 20) + (size_t)d * nTokS + nst] = u;
        }
    }
}

// ---------------- merged scores: fused exp -> P fp16; partial row sums ----------------
__global__ __launch_bounds__(256) void k_scores(
    const __half* __restrict__ qt, const __half* __restrict__ kt,
    __half* __restrict__ P, float* __restrict__ S3, float* __restrict__ rps)
{
    extern __shared__ __half dynsmem[];
    int f = blockIdx.x;
    int s, b, zS, sp = 0, bx, by;
    if (f < 4096)      { s = 0; zS = f >> 10; b = zS; int t = f & 1023; by = t >> 5; bx = t & 31; }
    else if (f < 4352) { s = 1; int r = f - 4096; zS = r >> 6; b = zS; int t = r & 63; by = t >> 3; bx = t & 7; }
    else if (f < 4368) { s = 2; int r = f - 4352; zS = r >> 2; b = zS; int t = r & 3; by = t >> 1; bx = t & 1; }
    else               { s = 3; int zz = f - 4368; zS = zz; b = zz >> 6; sp = zz & 63; bx = 0; by = 0; }

    int nTok = nssF(s), d = dssF(s);
    int Kl = (s == 3) ? 256 : d;
    const __half* Ab = qt + (size_t)b * TOKB + ((size_t)s << 20) + (size_t)sp * 256;
    const __half* Bb = kt + (size_t)b * TOKB + ((size_t)s << 20) + (size_t)sp * 256;
    int m0 = by * 128, n0 = bx * 128;

    float acc[4][4][4];
    mainloop128(Ab, Bb, d, d, Kl / KC, nTok - 1, nTok - 1, m0, n0,
                dynsmem, dynsmem + ST * 128 * RPH, acc);

    int tid = threadIdx.x, lane = tid & 31, wid = tid >> 5;
    int wm = wid >> 2, wn = wid & 3;
    int g = lane >> 2, q2 = (lane & 3) << 1;

    if (s < 3) {
        __syncthreads();
        float* sred = (float*)dynsmem;
        float alpha = rsqrtf((float)d);
        __half* Pb = P + soffF(s) + (size_t)zS * nTok * nTok;
#pragma unroll
        for (int mt = 0; mt < 4; mt++) {
            int row0 = m0 + wm * 64 + mt * 16 + g;
#pragma unroll
            for (int e2 = 0; e2 < 2; e2++) {
                int row = row0 + e2 * 8;
                float rs = 0.f;
#pragma unroll
                for (int nt = 0; nt < 4; nt++) {
                    int col = n0 + wn * 32 + nt * 8 + q2;
                    float e0 = __expf(acc[mt][nt][e2 * 2 + 0] * alpha);
                    float e1 = __expf(acc[mt][nt][e2 * 2 + 1] * alpha);
                    rs += e0 + e1;
                    *(__half2*)&Pb[(size_t)row * nTok + col] = __floats2half2_rn(e0, e1);
                }
                rs += __shfl_xor_sync(0xffffffff, rs, 1);
                rs += __shfl_xor_sync(0xffffffff, rs, 2);
                if ((lane & 3) == 0)
                    sred[(wm * 64 + mt * 16 + g + e2 * 8) * 4 + wn] = rs;
            }
        }
        __syncthreads();
        if (tid < 128) {
            float tot = sred[tid * 4] + sred[tid * 4 + 1] + sred[tid * 4 + 2] + sred[tid * 4 + 3];
            int nb = nTok >> 7;
            int base = (s == 0) ? 0 : (s == 1 ? 131072 : 139264);
            rps[b * RPSB + base + (m0 + tid) * nb + bx] = tot;
        }
    } else {
        float* Sb = S3 + (size_t)zS * 4096;
#pragma unroll
        for (int mt = 0; mt < 4; mt++) {
            int row0 = m0 + wm * 64 + mt * 16 + g;
#pragma unroll
            for (int e2 = 0; e2 < 2; e2++) {
                int row = row0 + e2 * 8;
                if (row >= 64) continue;
#pragma unroll
                for (int nt = 0; nt < 4; nt++) {
                    int col = n0 + wn * 32 + nt * 8 + q2;
                    if (col >= 64) continue;
                    *(float2*)&Sb[(size_t)row * 64 + col] =
                        make_float2(acc[mt][nt][e2 * 2 + 0], acc[mt][nt][e2 * 2 + 1]);
                }
            }
        }
    }
}

// ---------------- norm: scale-3 only (split-reduce + exp + Z) ----------------
__global__ void k_norm3(const float* __restrict__ S3, __half* __restrict__ P3out,
                        float* __restrict__ invZ)
{
    __shared__ float red[128];
    int row = blockIdx.x;   // 0..63
    int b = blockIdx.y;
    int tid = threadIdx.x;
    float e = 0.f;
    if (tid < 64) {
        float sv = 0.f;
        for (int sp = 0; sp < 64; sp++)
            sv += S3[(size_t)((b << 6) + sp) * 4096 + row * 64 + tid];
        e = __expf(sv * 0.0078125f);   // alpha = 1/128
        P3out[SOFF3 + (size_t)b * 4096 + row * 64 + tid] = __float2half_rn(e);
    }
    red[tid] = e; __syncthreads();
    for (int st = 64; st; st >>= 1) { if (tid < st) red[tid] += red[tid + st]; __syncthreads(); }
    if (tid == 0) invZ[b * 5440 + 5376 + row] = 1.0f / red[0];
}

// ---------------- merged P@V: in-block invZ for s0-2 ----------------
__global__ __launch_bounds__(256) void k_pv(
    const __half* __restrict__ P, const __half* __restrict__ vt,
    const float* __restrict__ rps, const float* __restrict__ invZ,
    __half* __restrict__ attnT)
{
    extern __shared__ __half dynsmem[];
    int f = blockIdx.x;
    int s, b, bx, by;
    if (f < 256)      { s = 0; b = f >> 6; int t = f & 63; by = t >> 1; bx = t & 1; }
    else if (f < 512) { s = 1; int r = f - 256; b = r >> 6; int t = r & 63; by = t >> 3; bx = t & 7; }
    else if (f < 768) { s = 2; int r = f - 512; b = r >> 6; int t = r & 63; bx = t >> 1; by = t & 1; }
    else              { s = 3; int r = f - 768; b = r >> 7; bx = r & 127; by = 0; }

    int nTok = nssF(s), d = dssF(s);
    const __half* Ab = P + soffF(s) + (size_t)b * nTok * nTok;
    const __half* Bb = vt + (size_t)b * TOKB + ((size_t)s << 20);
    int m0 = by * 128, n0 = bx * 128;
    int tid = threadIdx.x;

    // in-block invZ for this block's rows (scales 0-2), beyond the stage buffers
    float* zsm = (float*)(dynsmem + ST * 256 * RPH);
    if (s < 3 && tid < 128) {
        int row = m0 + tid;
        int nb = nTok >> 7;
        int base = (s == 0) ? 0 : (s == 1 ? 131072 : 139264);
        float z = 0.f;
        for (int j = 0; j < nb; j++)
            z += rps[b * RPSB + base + row * nb + j];
        zsm[tid] = 1.0f / z;
    }

    float acc[4][4][4];
    mainloop128(Ab, Bb, nTok, nTok, nTok / KC, nTok - 1, d - 1, m0, n0,
                dynsmem, dynsmem + ST * 128 * RPH, acc);

    int lane = tid & 31, wid = tid >> 5;
    int wm = wid >> 2, wn = wid & 3;
    int g = lane >> 2, q2 = (lane & 3) << 1;

    int l = s + 1, msk = (1 << l) - 1, owlog = 7 - l;
    int colb = n0 + wn * 32;
    int pix = colb >> 6;
    int py = pix >> l, px = pix & msk;

#pragma unroll
    for (int mt = 0; mt < 4; mt++) {
        int row0 = m0 + wm * 64 + mt * 16 + g;
#pragma unroll
        for (int e2 = 0; e2 < 2; e2++) {
            int row = row0 + e2 * 8;
            if (row >= nTok) continue;
            float iz = (s < 3) ? zsm[row - m0] : __ldg(&invZ[b * 5440 + 5376 + row]);
            int wy = row >> owlog, wx = row & ((1 << owlog) - 1);
            int y = (wy << l) | py, x = (wx << l) | px;
            size_t pbase = ((((size_t)b << 14) + (y << 7) + x) << 8) + (s << 6);
#pragma unroll
            for (int nt = 0; nt < 4; nt++) {
                int cl = (colb + nt * 8 + q2) & 63;
                __half v0 = __float2half_rn(acc[mt][nt][e2 * 2 + 0] * iz);
                __half v1 = __float2half_rn(acc[mt][nt][e2 * 2 + 1] * iz);
                *(__half2*)&attnT[pbase + cl] = __halves2half2(v0, v1);
            }
        }
    }
}

// ---------------- conv3x3 tap-GEMM + channel stats partials (R14 ordering) ----------
__global__ __launch_bounds__(256) void k_conv(
    const __half* __restrict__ Wo, const __half* __restrict__ attnT,
    const float* __restrict__ bo, float* __restrict__ out,
    float* __restrict__ cs, float* __restrict__ cs2)
{
    extern __shared__ __half dynsmem[];
    __half* Asm = dynsmem;
    __half* Bsm = dynsmem + ST * 128 * RPH;
    int tid = threadIdx.x;
    int lane = tid & 31, wid = tid >> 5;
    int wm = wid >> 2, wn = wid & 3;
    int m0 = blockIdx.y * 128, n0 = blockIdx.x * 128;
    int bidx = blockIdx.z;
    const __half* Ab = Wo;
    const __half* Bb = attnT + (size_t)bidx * CHW;

    uint32_t sA = (uint32_t)__cvta_generic_to_shared(Asm);
    uint32_t sB = (uint32_t)__cvta_generic_to_shared(Bsm);
    const uint32_t ASTR = 128 * RPH * 2, BSTR = 128 * RPH * 2;
    const int nc = 36;

    auto issue = [&](int c) {
        int st = c % ST;
        int k0 = c * KC;
#pragma unroll
        for (int j = 0; j < 4; j++) {
            int i = tid + j * 256;
            int row = i >> 3, seg = (i & 7) << 3;
            cpasync16(sA + st * ASTR + (uint32_t)(row * RPH + seg) * 2,
                      Ab + (size_t)(m0 + row) * 2304 + k0 + seg);
        }
        int tap = k0 >> 8;
        int dy = tap / 3, dx = tap - dy * 3;
        int gy = (int)blockIdx.x + dy - 1;
        bool okY = (unsigned)gy < 128u;
#pragma unroll
        for (int j = 0; j < 4; j++) {
            int i = tid + j * 256;
            int xrow = i >> 3, seg = (i & 7) << 3;
            int ch = (k0 & 255) + seg;
            int gx = xrow + dx - 1;
            int sz = (okY && (unsigned)gx < 128u) ? 16 : 0;
            const __half* src = Bb + ((size_t)(gy << 7) + gx) * 256 + ch;
            cpasync16z(sB + st * BSTR + (uint32_t)(xrow * RPH + seg) * 2, src, sz);
        }
    };

    float acc[4][4][4];
#pragma unroll
    for (int i = 0; i < 4; i++)
#pragma unroll
        for (int j = 0; j < 4; j++)
#pragma unroll
            for (int e = 0; e < 4; e++) acc[i][j][e] = 0.f;

    int r8 = lane & 7, hi8 = (lane >> 3) & 1, hi16 = (lane >> 4) & 1;
    uint32_t aOff = (uint32_t)((wm * 64 + r8 + hi8 * 8) * RPH * 2 + hi16 * 16);
    uint32_t bOff = (uint32_t)((wn * 32 + r8 + hi8 * 8) * RPH * 2 + hi16 * 16);

    issue(0);
    asm volatile("cp.async.commit_group;");
    issue(1);
    asm volatile("cp.async.commit_group;");

    for (int c = 0; c < nc; c++) {
        asm volatile("cp.async.wait_group 1;");
        __syncthreads();
        {
            int st = c % ST;
            uint32_t sa = sA + st * ASTR, sb = sB + st * BSTR;
#pragma unroll
            for (int ks = 0; ks < 4; ks++) {
                uint32_t af[4][4], bf[2][4];
#pragma unroll
                for (int mt = 0; mt < 4; mt++)
                    ldsm4(sa + aOff + mt * 16 * RPH * 2 + ks * 32, af[mt][0], af[mt][1], af[mt][2], af[mt][3]);
#pragma unroll
                for (int np = 0; np < 2; np++)
                    ldsm4(sb + bOff + np * 16 * RPH * 2 + ks * 32, bf[np][0], bf[np][1], bf[np][2], bf[np][3]);
#pragma unroll
                for (int mt = 0; mt < 4; mt++)
#pragma unroll
                    for (int np = 0; np < 2; np++) {
                        uint32_t b0[2] = { bf[np][0], bf[np][2] };
                        uint32_t b1[2] = { bf[np][1], bf[np][3] };
                        mma_f16(acc[mt][np * 2 + 0], af[mt], b0);
                        mma_f16(acc[mt][np * 2 + 1], af[mt], b1);
                    }
            }
        }
        if (c + 2 < nc) issue(c + 2);
        asm volatile("cp.async.commit_group;");
    }

    __syncthreads();
    float* sred  = (float*)dynsmem;
    float* sred2 = sred + 512;
    int g = lane >> 2, q2 = (lane & 3) << 1;
#pragma unroll
    for (int mt = 0; mt < 4; mt++) {
        int row0 = m0 + wm * 64 + mt * 16 + g;
#pragma unroll
        for (int e2 = 0; e2 < 2; e2++) {
            int row = row0 + e2 * 8;
            float bia = __ldg(&bo[row]);
            float rs = 0.f, rs2 = 0.f;
#pragma unroll
            for (int nt = 0; nt < 4; nt++) {
                int col = n0 + wn * 32 + nt * 8 + q2;
                float v0 = acc[mt][nt][e2 * 2 + 0] + bia;
                float v1 = acc[mt][nt][e2 * 2 + 1] + bia;
                rs += v0 + v1;
                rs2 += v0 * v0 + v1 * v1;
                size_t adr = (((size_t)bidx * 256 + row) << 14) + col;
                *(float2*)&out[adr] = make_float2(v0, v1);
            }
            rs  += __shfl_xor_sync(0xffffffff, rs, 1);
            rs  += __shfl_xor_sync(0xffffffff, rs, 2);
            rs2 += __shfl_xor_sync(0xffffffff, rs2, 1);
            rs2 += __shfl_xor_sync(0xffffffff, rs2, 2);
            if ((lane & 3) == 0) {
                int rl = wm * 64 + mt * 16 + g + e2 * 8;
                sred[rl * 4 + wn]  = rs;
                sred2[rl * 4 + wn] = rs2;
            }
        }
    }
    __syncthreads();
    if (tid < 128) {
        float s1 = sred[tid * 4] + sred[tid * 4 + 1] + sred[tid * 4 + 2] + sred[tid * 4 + 3];
        float s2 = sred2[tid * 4] + sred2[tid * 4 + 1] + sred2[tid * 4 + 2] + sred2[tid * 4 + 3];
        int ch = m0 + tid;
        int slot = bidx * 128 + blockIdx.x;
        cs[ch * 512 + slot]  = s1;
        cs2[ch * 512 + slot] = s2;
    }
}

// ---------------- prep: weights + transposes in ONE launch ----------------
__global__ void k_prep(const float* __restrict__ xs, const float* __restrict__ ys,
                       const float* __restrict__ wq, const float* __restrict__ wk,
                       const float* __restrict__ wv, const float* __restrict__ wo,
                       __half* __restrict__ xd, __half* __restrict__ yd,
                       __half* __restrict__ dq, __half* __restrict__ dk,
                       __half* __restrict__ dv, __half* __restrict__ dwo)
{
    if (blockIdx.z < 8) {
        __shared__ float t[32][33];
        int zz = blockIdx.z;
        int b = zz & 3;
        const float* s = ((zz >> 2) ? ys : xs) + (size_t)b * CHW;
        __half* d = ((zz >> 2) ? yd : xd) + (size_t)b * CHW;
        int tx = threadIdx.x & 31, ty = threadIdx.x >> 5;
        int x = blockIdx.x * 32 + tx;
        int yc = blockIdx.y * 32 + ty;
#pragma unroll
        for (int j = 0; j < 4; j++)
            t[ty + j * 8][tx] = s[(size_t)(yc + j * 8) * HWP + x];
        __syncthreads();
        int x2 = blockIdx.y * 32 + tx;
        int y2 = blockIdx.x * 32 + ty;
#pragma unroll
        for (int j = 0; j < 4; j++)
            d[(size_t)(y2 + j * 8) * 256 + x2] = __float2half_rn(t[tx][ty + j * 8]);
    } else {
        int flat = blockIdx.x + blockIdx.y * 512;
        if (flat >= 3072) return;
        int i = flat * 256 + threadIdx.x;
        if (i < 65536) dq[i] = __float2half_rn(wq[i]);
        else if (i < 131072) dk[i - 65536] = __float2half_rn(wk[i - 65536]);
        else if (i < 196608) dv[i - 131072] = __float2half_rn(wv[i - 131072]);
        else {
            int j = i - 196608;
            if (j < 589824) {
                int o = j / 2304, r = j - o * 2304;
                int tap = r >> 8, c = r & 255;
                dwo[j] = __float2half_rn(wo[((size_t)o * 256 + c) * 9 + tap]);
            }
        }
    }
}

// ---------------- batchnorm stats from conv partials ----------------
__global__ void k_stats(const float* __restrict__ cs, const float* __restrict__ cs2,
                        float* __restrict__ meanv, float* __restrict__ rstdv)
{
    __shared__ float rs[256], rs2[256];
    int c = blockIdx.x;
    int tid = threadIdx.x;
    float s  = cs[c * 512 + tid]  + cs[c * 512 + 256 + tid];
    float s2 = cs2[c * 512 + tid] + cs2[c * 512 + 256 + tid];
    rs[tid] = s; rs2[tid] = s2; __syncthreads();
    for (int st = 128; st; st >>= 1) {
        if (tid < st) { rs[tid] += rs[tid + st]; rs2[tid] += rs2[tid + st]; }
        __syncthreads();
    }
    if (tid == 0) {
        float m = rs[0] * (1.0f / 65536.0f);
        float var = rs2[0] * (1.0f / 65536.0f) - m * m;
        meanv[c] = m;
        rstdv[c] = rsqrtf(var + 1e-5f);
    }
}

// ---------------- normalize + affine + LeakyReLU ----------------
__global__ void k_final(float* __restrict__ z, const float* __restrict__ meanv, const float* __restrict__ rstdv,
                        const float* __restrict__ gamma, const float* __restrict__ beta)
{
    size_t idx = ((size_t)blockIdx.x * 1024 + threadIdx.x) * 4;
    int c = (int)((idx >> 14) & 255);
    float m = __ldg(&meanv[c]);
    float sc = __ldg(&rstdv[c]) * __ldg(&gamma[c]);
    float bt = __ldg(&beta[c]);
    float4 v = *(float4*)&z[idx];
    v.x = (v.x - m) * sc + bt; v.y = (v.y - m) * sc + bt;
    v.z = (v.z - m) * sc + bt; v.w = (v.w - m) * sc + bt;
    v.x = v.x >= 0.f ? v.x : 0.2f * v.x;
    v.y = v.y >= 0.f ? v.y : 0.2f * v.y;
    v.z = v.z >= 0.f ? v.z : 0.2f * v.z;
    v.w = v.w >= 0.f ? v.w : 0.2f * v.w;
    *(float4*)&z[idx] = v;
}

// ---------------- host launch ----------------
extern "C" void kernel_launch(void* const* d_in, const int* in_sizes, int n_in,
                              void* d_out, int out_size)
{
    (void)in_sizes; (void)n_in; (void)out_size;
    const float* x     = (const float*)d_in[0];
    const float* y     = (const float*)d_in[1];
    const float* Wq    = (const float*)d_in[2];
    const float* bq    = (const float*)d_in[3];
    const float* Wk    = (const float*)d_in[4];
    const float* bk    = (const float*)d_in[5];
    const float* Wv    = (const float*)d_in[6];
    const float* bv    = (const float*)d_in[7];
    const float* Wo    = (const float*)d_in[8];
    const float* bo    = (const float*)d_in[9];
    const float* gamma = (const float*)d_in[10];
    const float* beta  = (const float*)d_in[11];
    float* out = (float*)d_out;

    __half *qt, *kt, *vt, *P, *attnT, *xT, *yT, *WqH, *WkH, *WvH, *WoH;
    float *S3, *invZ, *rps, *cs, *cs2, *meanv, *rstdv;
    cudaGetSymbolAddress((void**)&qt,    g_qt);
    cudaGetSymbolAddress((void**)&kt,    g_kt);
    cudaGetSymbolAddress((void**)&vt,    g_vt);
    cudaGetSymbolAddress((void**)&S3,    g_S3);
    cudaGetSymbolAddress((void**)&P,     g_P);
    cudaGetSymbolAddress((void**)&invZ,  g_invZ);
    cudaGetSymbolAddress((void**)&rps,   g_rps);
    cudaGetSymbolAddress((void**)&cs,    g_cs);
    cudaGetSymbolAddress((void**)&cs2,   g_cs2);
    cudaGetSymbolAddress((void**)&attnT, g_attnT);
    cudaGetSymbolAddress((void**)&xT,    g_xT);
    cudaGetSymbolAddress((void**)&yT,    g_yT);
    cudaGetSymbolAddress((void**)&WqH,   g_WqH);
    cudaGetSymbolAddress((void**)&WkH,   g_WkH);
    cudaGetSymbolAddress((void**)&WvH,   g_WvH);
    cudaGetSymbolAddress((void**)&WoH,   g_WoH);
    cudaGetSymbolAddress((void**)&meanv, g_mean);
    cudaGetSymbolAddress((void**)&rstdv, g_rstd);

    const int shm  = ST * (128 + 128) * RPH * 2;   // 110592
    const int shmZ = shm + 512;                    // pv: + zsm[128]
    cudaFuncSetAttribute(k_proj,   cudaFuncAttributeMaxDynamicSharedMemorySize, shm);
    cudaFuncSetAttribute(k_scores, cudaFuncAttributeMaxDynamicSharedMemorySize, shm);
    cudaFuncSetAttribute(k_pv,     cudaFuncAttributeMaxDynamicSharedMemorySize, shmZ);
    cudaFuncSetAttribute(k_conv,   cudaFuncAttributeMaxDynamicSharedMemorySize, shm);

    // prep (weights + transposes, one launch)
    k_prep<<<dim3(512, 8, 9), 256>>>(x, y, Wq, Wk, Wv, Wo, xT, yT, WqH, WkH, WvH, WoH);

    // merged stages
    k_proj<<<dim3(2, 128, 12), 256, shm>>>(WqH, WkH, WvH, xT, yT, bq, bk, bv, qt, kt, vt);
    k_scores<<<4624, 256, shm>>>(qt, kt, P, S3, rps);
    k_norm3<<<dim3(64, 4), 128>>>(S3, P, invZ);
    k_pv<<<1280, 256, shmZ>>>(P, vt, rps, invZ, attnT);
    k_conv<<<dim3(128, 2, 4), 256, shm>>>(WoH, attnT, bo, out, cs, cs2);
    k_stats<<<256, 256>>>(cs, cs2, meanv, rstdv);
    k_final<<<4096, 1024>>>(out, meanv, rstdv, gamma, beta);
}